// round 1
// baseline (speedup 1.0000x reference)
#include <cuda_runtime.h>
#include <cuda_bf16.h>
#include <math.h>

#define NN 50000          // nodes
#define E2 400000         // directed edges
#define FD 3
#define HID 32
#define FH 96             // FD*HID
#define INCH 128
#define OUTCH 32

// ---------------- device scratch (static, no allocation) ----------------
__device__ float g_xc[NN * FH];        // xc / x0 (aliased in reference)
__device__ float g_y[NN * FH];         // transformed y
__device__ float g_PA[NN], g_PB[NN], g_WA[NN], g_WB[NN];
__device__ float g_deg[NN], g_dinv[NN];
__device__ int   g_cnt[NN];
__device__ int   g_off[NN + 1];
__device__ int   g_cur[NN];
__device__ int   g_e2pos[E2];
__device__ int   g_colc[E2];           // col in CSR order
__device__ float g_w2c[E2], g_Tcc[E2], g_Tsc[E2];
__device__ float g_Wl[2][9];
__device__ float g_Wr[2][1024];
__device__ float g_coeff[2][3];

// ---------------- helpers ----------------
__device__ __forceinline__ float eluf(float v) { return v > 0.f ? v : expm1f(v); }
__device__ __forceinline__ float sigm(float v) { return 1.f / (1.f + expf(-v)); }
__device__ __forceinline__ float wsum(float v) {
#pragma unroll
    for (int o = 16; o > 0; o >>= 1) v += __shfl_xor_sync(0xffffffffu, v, o);
    return v;
}

// ---------------- CSR build ----------------
__global__ void k_zero_cnt() {
    int i = blockIdx.x * blockDim.x + threadIdx.x;
    if (i < NN) g_cnt[i] = 0;
}
__global__ void k_count(const int* __restrict__ ei) {
    int e = blockIdx.x * blockDim.x + threadIdx.x;
    if (e < E2) atomicAdd(&g_cnt[ei[e]], 1);
}
__global__ void k_scan() {
    __shared__ int s[1024];
    int t = threadIdx.x;
    const int CH = (NN + 1023) / 1024;  // 49
    int base = t * CH;
    int local = 0;
    for (int i = 0; i < CH; i++) {
        int n = base + i;
        if (n < NN) local += g_cnt[n];
    }
    s[t] = local;
    __syncthreads();
    for (int d = 1; d < 1024; d <<= 1) {
        int v = (t >= d) ? s[t - d] : 0;
        __syncthreads();
        s[t] += v;
        __syncthreads();
    }
    int run = s[t] - local;  // exclusive prefix
    for (int i = 0; i < CH; i++) {
        int n = base + i;
        if (n < NN) {
            g_off[n] = run;
            g_cur[n] = run;
            run += g_cnt[n];
        }
    }
    if (t == 1023) g_off[NN] = s[1023];
}
__global__ void k_scatter(const int* __restrict__ ei) {
    int e = blockIdx.x * blockDim.x + threadIdx.x;
    if (e < E2) {
        int r = ei[e];
        int p = atomicAdd(&g_cur[r], 1);
        g_e2pos[e] = p;
        g_colc[p] = ei[E2 + e];
    }
}

// ---------------- spectral norm (per layer block) ----------------
__global__ void k_specnorm(const float* __restrict__ W_left,
                           const float* __restrict__ W_right,
                           const float* __restrict__ eps) {
    int layer = blockIdx.x;
    int lane = threadIdx.x;  // 32 threads
    __shared__ float ws[32 * 33];
    for (int i = lane; i < 1024; i += 32) {
        int r = i >> 5, c = i & 31;
        ws[r * 33 + c] = W_right[layer * 1024 + i];
    }
    __syncwarp();
    float u = 1.f / sqrtf(32.f);
    for (int it = 0; it < 20; it++) {
        float v = 0.f;
#pragma unroll 8
        for (int i = 0; i < 32; i++) v += ws[i * 33 + lane] * __shfl_sync(0xffffffffu, u, i);
        float nv = sqrtf(wsum(v * v));
        v = v / (nv + 1e-12f);
        float un = 0.f;
#pragma unroll 8
        for (int j = 0; j < 32; j++) un += ws[lane * 33 + j] * __shfl_sync(0xffffffffu, v, j);
        float nu = sqrtf(wsum(un * un));
        u = un / (nu + 1e-12f);
    }
    float v = 0.f;
    for (int i = 0; i < 32; i++) v += ws[i * 33 + lane] * __shfl_sync(0xffffffffu, u, i);
    float nv = sqrtf(wsum(v * v));
    v = v / (nv + 1e-12f);
    float wv = 0.f;
    for (int j = 0; j < 32; j++) wv += ws[lane * 33 + j] * __shfl_sync(0xffffffffu, v, j);
    float sigma = wsum(u * wv);
    float inv = 1.f / sigma;
    for (int i = lane; i < 1024; i += 32)
        g_Wr[layer][i] = W_right[layer * 1024 + i] * inv;

    if (lane == 0) {
        float W[9];
        for (int i = 0; i < 9; i++) W[i] = W_left[layer * 9 + i];
        float uu[3] = {0.5773502691896258f, 0.5773502691896258f, 0.5773502691896258f};
        float vv[3];
        for (int it = 0; it < 20; it++) {
            vv[0] = vv[1] = vv[2] = 0.f;
            for (int i = 0; i < 3; i++)
                for (int j = 0; j < 3; j++) vv[j] += W[i * 3 + j] * uu[i];
            float n2 = sqrtf(vv[0] * vv[0] + vv[1] * vv[1] + vv[2] * vv[2]) + 1e-12f;
            for (int j = 0; j < 3; j++) vv[j] /= n2;
            float u2[3] = {0.f, 0.f, 0.f};
            for (int i = 0; i < 3; i++)
                for (int j = 0; j < 3; j++) u2[i] += W[i * 3 + j] * vv[j];
            float n3 = sqrtf(u2[0] * u2[0] + u2[1] * u2[1] + u2[2] * u2[2]) + 1e-12f;
            for (int i = 0; i < 3; i++) uu[i] = u2[i] / n3;
        }
        vv[0] = vv[1] = vv[2] = 0.f;
        for (int i = 0; i < 3; i++)
            for (int j = 0; j < 3; j++) vv[j] += W[i * 3 + j] * uu[i];
        float n2 = sqrtf(vv[0] * vv[0] + vv[1] * vv[1] + vv[2] * vv[2]) + 1e-12f;
        for (int j = 0; j < 3; j++) vv[j] /= n2;
        float sig = 0.f;
        for (int i = 0; i < 3; i++) {
            float t = 0.f;
            for (int j = 0; j < 3; j++) t += W[i * 3 + j] * vv[j];
            sig += uu[i] * t;
        }
        float is = 1.f / sig;
        for (int i = 0; i < 9; i++) g_Wl[layer][i] = W[i] * is;
        for (int f = 0; f < 3; f++) g_coeff[layer][f] = 1.f + tanhf(eps[layer * 3 + f]);
    }
}

// ---------------- lin1: xc = elu(x @ W1^T + b1) ----------------
// block: 96 threads (one output col each), 16 nodes per tile, W1 chunk in smem
__global__ void k_lin1(const float* __restrict__ x, const float* __restrict__ W1,
                       const float* __restrict__ b1) {
    __shared__ float xs[16 * 128];
    __shared__ float ws[64 * 97];
    int t = threadIdx.x;  // 0..95
    float bo = b1[t];
    for (int tile = blockIdx.x; tile < NN / 16; tile += gridDim.x) {
        int n0 = tile * 16;
        for (int i = t; i < 16 * 128; i += 96) xs[i] = x[n0 * 128 + i];
        float acc[16];
#pragma unroll
        for (int nl = 0; nl < 16; nl++) acc[nl] = bo;
        for (int kc = 0; kc < 2; kc++) {
            __syncthreads();
            for (int i = t; i < 96 * 64; i += 96) {
                int o = i >> 6, kk = i & 63;
                ws[kk * 97 + o] = W1[o * 128 + kc * 64 + kk];
            }
            __syncthreads();
            for (int kk = 0; kk < 64; kk++) {
                float w = ws[kk * 97 + t];
                int kidx = kc * 64 + kk;
#pragma unroll
                for (int nl = 0; nl < 16; nl++) acc[nl] += xs[nl * 128 + kidx] * w;
            }
        }
#pragma unroll
        for (int nl = 0; nl < 16; nl++) {
            float v = acc[nl];
            g_xc[(n0 + nl) * FH + t] = v > 0.f ? v : expm1f(v);
        }
        __syncthreads();
    }
}

// ---------------- node projections (sheaf + weight learners) ----------------
__global__ void k_nodeproj(const float* __restrict__ W_sheaf,
                           const float* __restrict__ W_wt, int layer) {
    __shared__ float wa[96], wb[96], va[96], vb[96];
    int t = threadIdx.x;  // 128
    const float* ws1 = W_sheaf + layer * (3 * 192) + 192;  // row 1 only matters (D=2)
    const float* ww = W_wt + layer * 192;
    if (t < 96) {
        wa[t] = ws1[t];
        wb[t] = ws1[96 + t];
        va[t] = ww[t];
        vb[t] = ww[96 + t];
    }
    __syncthreads();
    int warp = t >> 5, lane = t & 31;
    int n = blockIdx.x * 4 + warp;
    if (n < NN) {
        float pa = 0.f, pb = 0.f, qa = 0.f, qb = 0.f;
#pragma unroll
        for (int k = lane; k < 96; k += 32) {
            float xv = g_xc[n * FH + k];
            pa += xv * wa[k];
            pb += xv * wb[k];
            qa += xv * va[k];
            qb += xv * vb[k];
        }
        pa = wsum(pa); pb = wsum(pb); qa = wsum(qa); qb = wsum(qb);
        if (lane == 0) {
            g_PA[n] = pa; g_PB[n] = pb; g_WA[n] = qa; g_WB[n] = qb;
        }
    }
}

// ---------------- per-edge scalars: w^2, transport rotation ----------------
__global__ void k_edge1(const int* __restrict__ ei) {
    int e = blockIdx.x * blockDim.x + threadIdx.x;
    if (e >= E2) return;
    int r = ei[e], c = ei[E2 + e];
    float w = sigm(g_WA[r] + g_WB[c]) * sigm(g_WA[c] + g_WB[r]);
    float a = tanhf(g_PA[r] + g_PB[c]);
    float ar = tanhf(g_PA[c] + g_PB[r]);
    float i1 = 1.f / (1.f + a * a), i2 = 1.f / (1.f + ar * ar);
    float ct = (1.f - a * a) * i1, st = 2.f * a * i1;
    float cr = (1.f - ar * ar) * i2, sr = 2.f * ar * i2;
    int p = g_e2pos[e];
    g_w2c[p] = w * w;
    g_Tcc[p] = ct * cr + st * sr;   // cos(theta_rev - theta)
    g_Tsc[p] = ct * sr - st * cr;   // sin(theta_rev - theta)
}

// ---------------- degree + dinv (warp per node over CSR) ----------------
__global__ void k_degdinv() {
    int warp = threadIdx.x >> 5, lane = threadIdx.x & 31;
    int n = blockIdx.x * 8 + warp;
    if (n >= NN) return;
    int s = g_off[n], e = g_off[n + 1];
    float sum = 0.f;
    for (int p = s + lane; p < e; p += 32) sum += g_w2c[p];
    sum = wsum(sum);
    if (lane == 0) {
        g_deg[n] = sum;
        g_dinv[n] = sum > 0.f ? rsqrtf(fmaxf(sum, 1e-30f)) : 0.f;
    }
}

// ---------------- y = Wl @ Y @ Wr^T per node ----------------
__global__ void k_ytrans(int layer) {
    __shared__ float wrt[32 * 32];  // wrt[h*32+c] = Wr[c*32+h]
    __shared__ float wl[9];
    __shared__ float ysh[96];
    __shared__ float tmpsh[96];
    int t = threadIdx.x;  // 96
    for (int i = t; i < 1024; i += 96) {
        int c = i >> 5, h = i & 31;
        wrt[h * 32 + c] = g_Wr[layer][i];
    }
    if (t < 9) wl[t] = g_Wl[layer][t];
    __syncthreads();
    int f = t / 32, c = t & 31;
    float w0 = 0, w1 = 0, w2v = 0;
    w0 = wl[f * 3 + 0]; w1 = wl[f * 3 + 1]; w2v = wl[f * 3 + 2];
    for (int n = blockIdx.x; n < NN; n += gridDim.x) {
        ysh[t] = g_xc[n * FH + t];
        __syncthreads();
        tmpsh[t] = w0 * ysh[c] + w1 * ysh[32 + c] + w2v * ysh[64 + c];
        __syncthreads();
        float acc = 0.f;
#pragma unroll
        for (int h = 0; h < 32; h++) acc += tmpsh[f * 32 + h] * wrt[h * 32 + c];
        g_y[n * FH + t] = acc;
        __syncthreads();
    }
}

// ---------------- fused Laplacian apply + ELU + residual update ----------------
__global__ void k_aggupdate(int layer) {
    int warp = threadIdx.x >> 5, lane = threadIdx.x & 31;
    int n = blockIdx.x * 8 + warp;
    if (n >= NN) return;
    float acc0 = 0.f, acc1 = 0.f, acc2 = 0.f;
    int s = g_off[n], e = g_off[n + 1];
    float dn = g_dinv[n];
    for (int p = s; p < e; p++) {
        int c = g_colc[p];
        float cn = g_w2c[p] * dn * g_dinv[c];
        float Tc = g_Tcc[p], Ts = g_Tsc[p];
        const float* yc = g_y + c * FH;
        float y0 = yc[lane], y1 = yc[32 + lane], y2 = yc[64 + lane];
        acc0 += cn * (Tc * y0 - Ts * y1);
        acc1 += cn * (Ts * y0 + Tc * y1);
        acc2 += cn * y2;
    }
    float diag = (g_deg[n] > 0.f) ? 1.f : 0.f;
    const float* yn = g_y + n * FH;
    float z0 = eluf(diag * yn[lane] - acc0);
    float z1 = eluf(diag * yn[32 + lane] - acc1);
    float z2 = eluf(diag * yn[64 + lane] - acc2);
    float c0 = g_coeff[layer][0], c1 = g_coeff[layer][1], c2 = g_coeff[layer][2];
    float* xn = g_xc + n * FH;
    xn[lane]      = c0 * xn[lane]      - z0;
    xn[32 + lane] = c1 * xn[32 + lane] - z1;
    xn[64 + lane] = c2 * xn[64 + lane] - z2;
}

// ---------------- lin2: out = xc @ W2^T + b2 ----------------
__global__ void k_lin2(const float* __restrict__ W2, const float* __restrict__ b2,
                       float* __restrict__ out) {
    __shared__ float w2t[96 * 32];  // w2t[k*32+o] = W2[o*96+k]
    __shared__ float xs[8][96];
    int t = threadIdx.x;
    for (int i = t; i < 96 * 32; i += 256) {
        int o = i / 96, k = i % 96;
        w2t[k * 32 + o] = W2[i];
    }
    __syncthreads();
    int warp = t >> 5, lane = t & 31;
    float bb = b2[lane];
    int n = blockIdx.x * 8 + warp;
    if (n >= NN) return;
    for (int k = lane; k < 96; k += 32) xs[warp][k] = g_xc[n * FH + k];
    __syncwarp();
    float acc = bb;
#pragma unroll
    for (int k = 0; k < 96; k++) acc += xs[warp][k] * w2t[k * 32 + lane];
    out[n * 32 + lane] = acc;
}

// ---------------- launcher ----------------
extern "C" void kernel_launch(void* const* d_in, const int* in_sizes, int n_in,
                              void* d_out, int out_size) {
    const float* x       = (const float*)d_in[0];
    const int*   ei      = (const int*)d_in[1];
    const float* W1      = (const float*)d_in[2];
    const float* b1      = (const float*)d_in[3];
    const float* W2      = (const float*)d_in[4];
    const float* b2      = (const float*)d_in[5];
    const float* W_left  = (const float*)d_in[6];
    const float* W_right = (const float*)d_in[7];
    const float* eps     = (const float*)d_in[8];
    const float* W_sheaf = (const float*)d_in[9];
    const float* W_wt    = (const float*)d_in[10];
    float* out = (float*)d_out;

    // CSR build (edge_index constant per launch)
    k_zero_cnt<<<(NN + 255) / 256, 256>>>();
    k_count<<<(E2 + 255) / 256, 256>>>(ei);
    k_scan<<<1, 1024>>>();
    k_scatter<<<(E2 + 255) / 256, 256>>>(ei);

    // spectral-normalized weights + coeffs (both layers)
    k_specnorm<<<2, 32>>>(W_left, W_right, eps);

    // lin1 + ELU
    k_lin1<<<NN / 16, 96>>>(x, W1, b1);

    for (int layer = 0; layer < 2; layer++) {
        k_nodeproj<<<(NN + 3) / 4, 128>>>(W_sheaf, W_wt, layer);
        k_edge1<<<(E2 + 255) / 256, 256>>>(ei);
        k_degdinv<<<(NN + 7) / 8, 256>>>();
        k_ytrans<<<6250, 96>>>(layer);
        k_aggupdate<<<(NN + 7) / 8, 256>>>(layer);
    }

    k_lin2<<<(NN + 7) / 8, 256>>>(W2, b2, out);
}

// round 4
// speedup vs baseline: 1.6274x; 1.6274x over previous
#include <cuda_runtime.h>
#include <cuda_bf16.h>
#include <math.h>

#define NN 50000          // nodes
#define E2 400000         // directed edges
#define FH 96             // FD*HID
#define NBLK 196          // ceil(NN/256)

typedef unsigned long long ull;

// ---------------- device scratch ----------------
__device__ float g_xc[NN * FH];
__device__ float g_y[NN * FH];
__device__ float4 g_n4[NN];            // {PA, PB, WA, WB}
__device__ float g_deg[NN], g_dinv[NN];
__device__ int   g_cnt[NN];
__device__ int   g_off[NN + 1];
__device__ int   g_cur[NN];
__device__ int   g_bsum[NBLK];
__device__ int   g_bbase[256];
__device__ int   g_rowc[E2];
__device__ int   g_colc[E2];
__device__ float4 g_e4[E2];            // {w2, Tc, Ts, bitcast(col)}
__device__ float g_Wl[2][9];
__device__ float g_WrT[2][1024];       // transposed: [h*32 + c]
__device__ float g_coeff[2][3];

// ---------------- helpers ----------------
__device__ __forceinline__ float eluf(float v) { return v > 0.f ? v : expm1f(v); }
__device__ __forceinline__ float sigm(float v) { return 1.f / (1.f + expf(-v)); }
__device__ __forceinline__ float wsum(float v) {
#pragma unroll
    for (int o = 16; o > 0; o >>= 1) v += __shfl_xor_sync(0xffffffffu, v, o);
    return v;
}
__device__ __forceinline__ void ffma2(ull& d, ull a, ull b) {
    asm("fma.rn.f32x2 %0, %1, %2, %0;" : "+l"(d) : "l"(a), "l"(b));
}
__device__ __forceinline__ ull pk2(float v) {
    ull r; asm("mov.b64 %0, {%1, %1};" : "=l"(r) : "f"(v)); return r;
}
__device__ __forceinline__ void upk2(float& lo, float& hi, ull v) {
    asm("mov.b64 {%0, %1}, %2;" : "=f"(lo), "=f"(hi) : "l"(v));
}

// ---------------- CSR build ----------------
__global__ void k_zero_cnt() {
    int i = blockIdx.x * blockDim.x + threadIdx.x;
    if (i < NN) g_cnt[i] = 0;
}
__global__ void k_count(const int* __restrict__ ei) {
    int e = blockIdx.x * blockDim.x + threadIdx.x;
    if (e < E2) atomicAdd(&g_cnt[ei[e]], 1);
}
__global__ void k_scanA() {
    __shared__ int s[256];
    int b = blockIdx.x, t = threadIdx.x, i = b * 256 + t;
    int v = (i < NN) ? g_cnt[i] : 0;
    s[t] = v;
    __syncthreads();
#pragma unroll
    for (int d = 1; d < 256; d <<= 1) {
        int x = (t >= d) ? s[t - d] : 0;
        __syncthreads();
        s[t] += x;
        __syncthreads();
    }
    if (i < NN) g_off[i] = s[t] - v;     // exclusive within block
    if (t == 255) g_bsum[b] = s[255];
}
__global__ void k_scanB() {
    __shared__ int s[256];
    int t = threadIdx.x;
    int v = (t < NBLK) ? g_bsum[t] : 0;
    s[t] = v;
    __syncthreads();
#pragma unroll
    for (int d = 1; d < 256; d <<= 1) {
        int x = (t >= d) ? s[t - d] : 0;
        __syncthreads();
        s[t] += x;
        __syncthreads();
    }
    g_bbase[t] = s[t] - v;
    if (t == 255) g_off[NN] = s[255];
}
__global__ void k_scanC() {
    int i = blockIdx.x * blockDim.x + threadIdx.x;
    if (i < NN) {
        int o = g_off[i] + g_bbase[i >> 8];
        g_off[i] = o;
        g_cur[i] = o;
    }
}
__global__ void k_scatter(const int* __restrict__ ei) {
    int e = blockIdx.x * blockDim.x + threadIdx.x;
    if (e < E2) {
        int r = ei[e];
        int p = atomicAdd(&g_cur[r], 1);
        g_rowc[p] = r;
        g_colc[p] = ei[E2 + e];
    }
}

// ---------------- spectral norm ----------------
__global__ void k_specnorm(const float* __restrict__ W_left,
                           const float* __restrict__ W_right,
                           const float* __restrict__ eps) {
    int layer = blockIdx.x;
    int lane = threadIdx.x;  // 32
    __shared__ float ws[32 * 33];
    for (int i = lane; i < 1024; i += 32) {
        int r = i >> 5, c = i & 31;
        ws[r * 33 + c] = W_right[layer * 1024 + i];
    }
    __syncwarp();
    float u = 1.f / sqrtf(32.f);
    for (int it = 0; it < 20; it++) {
        float v = 0.f;
#pragma unroll 8
        for (int i = 0; i < 32; i++) v += ws[i * 33 + lane] * __shfl_sync(0xffffffffu, u, i);
        float nv = sqrtf(wsum(v * v));
        v = v / (nv + 1e-12f);
        float un = 0.f;
#pragma unroll 8
        for (int j = 0; j < 32; j++) un += ws[lane * 33 + j] * __shfl_sync(0xffffffffu, v, j);
        float nu = sqrtf(wsum(un * un));
        u = un / (nu + 1e-12f);
    }
    float v = 0.f;
    for (int i = 0; i < 32; i++) v += ws[i * 33 + lane] * __shfl_sync(0xffffffffu, u, i);
    float nv = sqrtf(wsum(v * v));
    v = v / (nv + 1e-12f);
    float wv = 0.f;
    for (int j = 0; j < 32; j++) wv += ws[lane * 33 + j] * __shfl_sync(0xffffffffu, v, j);
    float sigma = wsum(u * wv);
    float inv = 1.f / sigma;
    for (int i = lane; i < 1024; i += 32) {
        int c = i >> 5, h = i & 31;
        g_WrT[layer][h * 32 + c] = W_right[layer * 1024 + i] * inv;
    }

    if (lane == 0) {
        float W[9];
        for (int i = 0; i < 9; i++) W[i] = W_left[layer * 9 + i];
        float uu[3] = {0.5773502691896258f, 0.5773502691896258f, 0.5773502691896258f};
        float vv[3];
        for (int it = 0; it < 20; it++) {
            vv[0] = vv[1] = vv[2] = 0.f;
            for (int i = 0; i < 3; i++)
                for (int j = 0; j < 3; j++) vv[j] += W[i * 3 + j] * uu[i];
            float n2 = sqrtf(vv[0] * vv[0] + vv[1] * vv[1] + vv[2] * vv[2]) + 1e-12f;
            for (int j = 0; j < 3; j++) vv[j] /= n2;
            float u2[3] = {0.f, 0.f, 0.f};
            for (int i = 0; i < 3; i++)
                for (int j = 0; j < 3; j++) u2[i] += W[i * 3 + j] * vv[j];
            float n3 = sqrtf(u2[0] * u2[0] + u2[1] * u2[1] + u2[2] * u2[2]) + 1e-12f;
            for (int i = 0; i < 3; i++) uu[i] = u2[i] / n3;
        }
        vv[0] = vv[1] = vv[2] = 0.f;
        for (int i = 0; i < 3; i++)
            for (int j = 0; j < 3; j++) vv[j] += W[i * 3 + j] * uu[i];
        float n2 = sqrtf(vv[0] * vv[0] + vv[1] * vv[1] + vv[2] * vv[2]) + 1e-12f;
        for (int j = 0; j < 3; j++) vv[j] /= n2;
        float sig = 0.f;
        for (int i = 0; i < 3; i++) {
            float t = 0.f;
            for (int j = 0; j < 3; j++) t += W[i * 3 + j] * vv[j];
            sig += uu[i] * t;
        }
        float is = 1.f / sig;
        for (int i = 0; i < 9; i++) g_Wl[layer][i] = W[i] * is;
        for (int f = 0; f < 3; f++) g_coeff[layer][f] = 1.f + tanhf(eps[layer * 3 + f]);
    }
}

// ---------------- lin1: xc = elu(x @ W1^T + b1), FFMA2 register tiling ----------------
// tile: 128 nodes x 96 cols; block 256 threads; thread = 8 nodes (4 f32x2 pairs) x 6 cols
#define XS_LD 134
#define WS_LD 98
__global__ void __launch_bounds__(256) k_lin1(const float* __restrict__ x,
                                              const float* __restrict__ W1,
                                              const float* __restrict__ b1) {
    __shared__ float xs_t[32 * XS_LD];   // [k][node]
    __shared__ float ws[32 * WS_LD];     // [k][out]
    int t = threadIdx.x;
    int tx = t & 15;        // col group: 6 cols
    int ty = t >> 4;        // node group: 8 nodes
    int nb = blockIdx.x * 128;

    ull acc[4][6];
#pragma unroll
    for (int i = 0; i < 4; i++)
#pragma unroll
        for (int j = 0; j < 6; j++) acc[i][j] = 0ull;

    for (int kc = 0; kc < 4; kc++) {
        __syncthreads();
        // load 128 nodes x 32 k of x
#pragma unroll
        for (int r = 0; r < 16; r++) {
            int idx = t + 256 * r;
            int n = idx >> 5, k = idx & 31;
            int ng = nb + n;
            float v = (ng < NN) ? x[ng * 128 + kc * 32 + k] : 0.f;
            xs_t[k * XS_LD + n] = v;
        }
        // load 96 x 32 of W1 (transposed into [k][o])
#pragma unroll
        for (int r = 0; r < 12; r++) {
            int idx = t + 256 * r;
            int o = idx >> 5, k = idx & 31;
            ws[k * WS_LD + o] = W1[o * 128 + kc * 32 + k];
        }
        __syncthreads();
#pragma unroll
        for (int k = 0; k < 32; k++) {
            ull a2[4];
#pragma unroll
            for (int i = 0; i < 4; i++)
                a2[i] = *reinterpret_cast<const ull*>(&xs_t[k * XS_LD + ty * 8 + 2 * i]);
#pragma unroll
            for (int j = 0; j < 6; j++) {
                ull b2 = pk2(ws[k * WS_LD + tx * 6 + j]);
#pragma unroll
                for (int i = 0; i < 4; i++) ffma2(acc[i][j], a2[i], b2);
            }
        }
    }
    // epilogue: bias + elu + store
    float bb[6];
#pragma unroll
    for (int j = 0; j < 6; j++) bb[j] = b1[tx * 6 + j];
#pragma unroll
    for (int i = 0; i < 4; i++) {
        int n0 = nb + ty * 8 + 2 * i;
#pragma unroll
        for (int j = 0; j < 6; j++) {
            float lo, hi;
            upk2(lo, hi, acc[i][j]);
            lo += bb[j]; hi += bb[j];
            int c = tx * 6 + j;
            if (n0 < NN)     g_xc[n0 * FH + c]       = lo > 0.f ? lo : expm1f(lo);
            if (n0 + 1 < NN) g_xc[(n0 + 1) * FH + c] = hi > 0.f ? hi : expm1f(hi);
        }
    }
}

// ---------------- fused node kernel: projections + y = Wl Y Wr^T ----------------
// warp per node, no smem, no syncthreads
__global__ void k_node(const float* __restrict__ W_sheaf,
                       const float* __restrict__ W_wt, int layer) {
    int lane = threadIdx.x & 31;
    int warpg = (blockIdx.x * blockDim.x + threadIdx.x) >> 5;
    int nwarps = (gridDim.x * blockDim.x) >> 5;

    const float* ws1 = W_sheaf + layer * 576 + 192;  // row 1 of sheaf learner (D=2)
    float wa0 = ws1[lane], wa1 = ws1[32 + lane], wa2 = ws1[64 + lane];
    float wb0 = ws1[96 + lane], wb1 = ws1[128 + lane], wb2 = ws1[160 + lane];
    const float* ww = W_wt + layer * 192;
    float va0 = ww[lane], va1 = ww[32 + lane], va2 = ww[64 + lane];
    float vb0 = ww[96 + lane], vb1 = ww[128 + lane], vb2 = ww[160 + lane];
    float wl[9];
#pragma unroll
    for (int i = 0; i < 9; i++) wl[i] = g_Wl[layer][i];
    float wrr[32];
#pragma unroll
    for (int h = 0; h < 32; h++) wrr[h] = g_WrT[layer][h * 32 + lane];

    for (int n = warpg; n < NN; n += nwarps) {
        const float* base = g_xc + n * FH;
        float y0 = base[lane], y1 = base[32 + lane], y2 = base[64 + lane];
        // projections
        float pa = y0 * wa0 + y1 * wa1 + y2 * wa2;
        float pb = y0 * wb0 + y1 * wb1 + y2 * wb2;
        float qa = y0 * va0 + y1 * va1 + y2 * va2;
        float qb = y0 * vb0 + y1 * vb1 + y2 * vb2;
        pa = wsum(pa); pb = wsum(pb); qa = wsum(qa); qb = wsum(qb);
        if (lane == 0) g_n4[n] = make_float4(pa, pb, qa, qb);
        // left mix (per-lane, no shuffles)
        float t0 = wl[0] * y0 + wl[1] * y1 + wl[2] * y2;
        float t1 = wl[3] * y0 + wl[4] * y1 + wl[5] * y2;
        float t2 = wl[6] * y0 + wl[7] * y1 + wl[8] * y2;
        // right mix: out_c = sum_h t[h] * Wr[c][h]
        float o0 = 0.f, o1 = 0.f, o2 = 0.f;
#pragma unroll
        for (int h = 0; h < 32; h++) {
            float s0 = __shfl_sync(0xffffffffu, t0, h);
            float s1 = __shfl_sync(0xffffffffu, t1, h);
            float s2 = __shfl_sync(0xffffffffu, t2, h);
            float w = wrr[h];
            o0 += s0 * w; o1 += s1 * w; o2 += s2 * w;
        }
        float* yo = g_y + n * FH;
        yo[lane] = o0; yo[32 + lane] = o1; yo[64 + lane] = o2;
    }
}

// ---------------- per-edge scalars over CSR order ----------------
__global__ void k_edge(int layer) {
    int p = blockIdx.x * blockDim.x + threadIdx.x;
    if (p >= E2) return;
    int r = g_rowc[p], c = g_colc[p];
    float4 A = g_n4[r], B = g_n4[c];
    float w = sigm(A.z + B.w) * sigm(B.z + A.w);
    float a = tanhf(A.x + B.y);
    float ar = tanhf(B.x + A.y);
    float i1 = 1.f / (1.f + a * a), i2 = 1.f / (1.f + ar * ar);
    float ct = (1.f - a * a) * i1, st = 2.f * a * i1;
    float cr = (1.f - ar * ar) * i2, sr = 2.f * ar * i2;
    float4 E;
    E.x = w * w;
    E.y = ct * cr + st * sr;   // cos(theta_rev - theta)
    E.z = ct * sr - st * cr;   // sin(theta_rev - theta)
    E.w = __int_as_float(c);
    g_e4[p] = E;
}

// ---------------- degree + dinv ----------------
__global__ void k_degdinv() {
    int warp = threadIdx.x >> 5, lane = threadIdx.x & 31;
    int n = blockIdx.x * 8 + warp;
    if (n >= NN) return;
    int s = g_off[n], e = g_off[n + 1];
    float sum = 0.f;
    for (int p = s + lane; p < e; p += 32) sum += g_e4[p].x;
    sum = wsum(sum);
    if (lane == 0) {
        g_deg[n] = sum;
        g_dinv[n] = sum > 0.f ? rsqrtf(fmaxf(sum, 1e-30f)) : 0.f;
    }
}

// ---------------- fused Laplacian apply + ELU + residual ----------------
__global__ void k_agg(int layer) {
    int warp = threadIdx.x >> 5, lane = threadIdx.x & 31;
    int n = blockIdx.x * 8 + warp;
    if (n >= NN) return;
    int s = g_off[n], e = g_off[n + 1];
    float dn = g_dinv[n];
    float acc0 = 0.f, acc1 = 0.f, acc2 = 0.f;
    int p = s;
    for (; p + 2 <= e; p += 2) {
        float4 E0 = g_e4[p], E1 = g_e4[p + 1];
        int c0 = __float_as_int(E0.w), c1 = __float_as_int(E1.w);
        float d0 = g_dinv[c0], d1 = g_dinv[c1];
        const float* yp0 = g_y + c0 * FH;
        const float* yp1 = g_y + c1 * FH;
        float ya0 = yp0[lane], ya1 = yp0[32 + lane], ya2 = yp0[64 + lane];
        float yb0 = yp1[lane], yb1 = yp1[32 + lane], yb2 = yp1[64 + lane];
        float cn0 = E0.x * dn * d0, cn1 = E1.x * dn * d1;
        acc0 += cn0 * (E0.y * ya0 - E0.z * ya1) + cn1 * (E1.y * yb0 - E1.z * yb1);
        acc1 += cn0 * (E0.z * ya0 + E0.y * ya1) + cn1 * (E1.z * yb0 + E1.y * yb1);
        acc2 += cn0 * ya2 + cn1 * yb2;
    }
    if (p < e) {
        float4 E0 = g_e4[p];
        int c0 = __float_as_int(E0.w);
        float d0 = g_dinv[c0];
        const float* yp0 = g_y + c0 * FH;
        float ya0 = yp0[lane], ya1 = yp0[32 + lane], ya2 = yp0[64 + lane];
        float cn0 = E0.x * dn * d0;
        acc0 += cn0 * (E0.y * ya0 - E0.z * ya1);
        acc1 += cn0 * (E0.z * ya0 + E0.y * ya1);
        acc2 += cn0 * ya2;
    }
    float diag = (g_deg[n] > 0.f) ? 1.f : 0.f;
    const float* yn = g_y + n * FH;
    float z0 = eluf(diag * yn[lane] - acc0);
    float z1 = eluf(diag * yn[32 + lane] - acc1);
    float z2 = eluf(diag * yn[64 + lane] - acc2);
    float c0 = g_coeff[layer][0], c1 = g_coeff[layer][1], c2 = g_coeff[layer][2];
    float* xn = g_xc + n * FH;
    xn[lane]      = c0 * xn[lane]      - z0;
    xn[32 + lane] = c1 * xn[32 + lane] - z1;
    xn[64 + lane] = c2 * xn[64 + lane] - z2;
}

// ---------------- lin2 ----------------
__global__ void k_lin2(const float* __restrict__ W2, const float* __restrict__ b2,
                       float* __restrict__ out) {
    __shared__ float w2t[96 * 32];
    __shared__ float xs[8][96];
    int t = threadIdx.x;
    for (int i = t; i < 96 * 32; i += 256) {
        int o = i / 96, k = i % 96;
        w2t[k * 32 + o] = W2[i];
    }
    __syncthreads();
    int warp = t >> 5, lane = t & 31;
    float bb = b2[lane];
    int n = blockIdx.x * 8 + warp;
    if (n >= NN) return;
    for (int k = lane; k < 96; k += 32) xs[warp][k] = g_xc[n * FH + k];
    __syncwarp();
    float acc = bb;
#pragma unroll
    for (int k = 0; k < 96; k++) acc += xs[warp][k] * w2t[k * 32 + lane];
    out[n * 32 + lane] = acc;
}

// ---------------- launcher ----------------
extern "C" void kernel_launch(void* const* d_in, const int* in_sizes, int n_in,
                              void* d_out, int out_size) {
    const float* x       = (const float*)d_in[0];
    const int*   ei      = (const int*)d_in[1];
    const float* W1      = (const float*)d_in[2];
    const float* b1      = (const float*)d_in[3];
    const float* W2      = (const float*)d_in[4];
    const float* b2      = (const float*)d_in[5];
    const float* W_left  = (const float*)d_in[6];
    const float* W_right = (const float*)d_in[7];
    const float* eps     = (const float*)d_in[8];
    const float* W_sheaf = (const float*)d_in[9];
    const float* W_wt    = (const float*)d_in[10];
    float* out = (float*)d_out;

    // CSR build
    k_zero_cnt<<<NBLK, 256>>>();
    k_count<<<(E2 + 255) / 256, 256>>>(ei);
    k_scanA<<<NBLK, 256>>>();
    k_scanB<<<1, 256>>>();
    k_scanC<<<NBLK, 256>>>();
    k_scatter<<<(E2 + 255) / 256, 256>>>(ei);

    k_specnorm<<<2, 32>>>(W_left, W_right, eps);

    k_lin1<<<(NN + 127) / 128, 256>>>(x, W1, b1);

    for (int layer = 0; layer < 2; layer++) {
        k_node<<<1024, 256>>>(W_sheaf, W_wt, layer);
        k_edge<<<(E2 + 255) / 256, 256>>>(layer);
        k_degdinv<<<(NN + 7) / 8, 256>>>();
        k_agg<<<(NN + 7) / 8, 256>>>(layer);
    }

    k_lin2<<<(NN + 7) / 8, 256>>>(W2, b2, out);
}